// round 3
// baseline (speedup 1.0000x reference)
#include <cuda_runtime.h>

#define HW_   1048576   // 1024*1024
#define W_    1024
#define H_    1024
#define NTR_  12

#define SW_   52        // staged tile max width/height (49 + 3 margin)
#define SP_   53        // smem row stride (odd -> conflict-free)
#define SCH_  (SW_ * SP_)  // per-channel smem floats

// Output float layout (out_size = 12*4*HW + 144):
//   xs   : [0, 12*3*HW)        (12,3,1024,1024)
//   os   : [12*3*HW, 12*4*HW)  (12,1,1024,1024)
//   z    : [12*4*HW, +72)   inv_z: [+72, +144)

__global__ void affine_params_kernel(const float* __restrict__ A,
                                     float* __restrict__ out) {
    int n = threadIdx.x;
    if (n >= NTR_) return;
    const float* t = A + n * 6;
    float a = t[0], b = t[1], tx = t[2];
    float c = t[3], d = t[4], ty = t[5];

    float* z  = out + (size_t)NTR_ * 4 * HW_;
    float* iz = z + NTR_ * 6;

    z[n*6+0] = a;  z[n*6+1] = b;  z[n*6+2] = tx;
    z[n*6+3] = c;  z[n*6+4] = d;  z[n*6+5] = ty;

    float inv = 1.0f / (a * d - b * c);
    float ia =  d * inv, ib = -b * inv;
    float ic = -c * inv, id =  a * inv;
    iz[n*6+0] = ia; iz[n*6+1] = ib; iz[n*6+2] = -(ia * tx + ib * ty);
    iz[n*6+3] = ic; iz[n*6+4] = id; iz[n*6+5] = -(ic * tx + id * ty);
}

// One block = one 32x32 output tile for one transform n.
// Stage the preimage bbox (3 channels, zero-filled outside image) into smem,
// then bilinear-sample from LDS. Threads: 256 = 32(w) x 8(h), 4 h-steps each.
__global__ void __launch_bounds__(256, 6)
sample_tile_kernel(const float* __restrict__ x,
                   const float* __restrict__ A,
                   float* __restrict__ out) {
    __shared__ float sm[3 * SCH_];

    const int n   = blockIdx.z;
    const int w0  = blockIdx.x << 5;
    const int h0  = blockIdx.y << 5;
    const int tid = threadIdx.x;

    const float t00 = __ldg(A + n*6 + 0);
    const float t01 = __ldg(A + n*6 + 1);
    const float t02 = __ldg(A + n*6 + 2);
    const float t10 = __ldg(A + n*6 + 3);
    const float t11 = __ldg(A + n*6 + 4);
    const float t12 = __ldg(A + n*6 + 5);

    // ix = t00*(w+0.5) + t01*(h+0.5) + cx ; iy likewise
    const float cx = 512.0f * (t02 - t00 - t01 + 1.0f) - 0.5f;
    const float cy = 512.0f * (t12 - t10 - t11 + 1.0f) - 0.5f;

    // Preimage bbox from the 4 tile-corner pixel centers (affine -> extremes at corners)
    const float wlo = (float)w0 + 0.5f, whi = (float)w0 + 31.5f;
    const float hlo = (float)h0 + 0.5f, hhi = (float)h0 + 31.5f;

    const float ix00 = fmaf(t00, wlo, fmaf(t01, hlo, cx));
    const float ix01 = fmaf(t00, wlo, fmaf(t01, hhi, cx));
    const float ix10 = fmaf(t00, whi, fmaf(t01, hlo, cx));
    const float ix11 = fmaf(t00, whi, fmaf(t01, hhi, cx));
    const float iy00 = fmaf(t10, wlo, fmaf(t11, hlo, cy));
    const float iy01 = fmaf(t10, wlo, fmaf(t11, hhi, cy));
    const float iy10 = fmaf(t10, whi, fmaf(t11, hlo, cy));
    const float iy11 = fmaf(t10, whi, fmaf(t11, hhi, cy));

    const float ixmin = fminf(fminf(ix00, ix01), fminf(ix10, ix11));
    const float ixmax = fmaxf(fmaxf(ix00, ix01), fmaxf(ix10, ix11));
    const float iymin = fminf(fminf(iy00, iy01), fminf(iy10, iy11));
    const float iymax = fmaxf(fmaxf(iy00, iy01), fmaxf(iy10, iy11));

    // +-1 margin guards floor() ulp disagreement vs per-pixel evaluation
    const int xmin = (int)floorf(ixmin) - 1;
    const int ymin = (int)floorf(iymin) - 1;
    int Wt = ((int)floorf(ixmax) + 2) - xmin + 1;
    int Ht = ((int)floorf(iymax) + 2) - ymin + 1;
    Wt = min(Wt, SW_);
    Ht = min(Ht, SW_);

    // ---- stage bbox into smem (zero outside image) ----
    {
        const int c  = tid & 31;
        int       r  = tid >> 5;            // 0..7, stride 8
        for (; r < Ht; r += 8) {
            const int  gy   = ymin + r;
            const bool vy   = ((unsigned)gy < (unsigned)H_);
            const int  grow = gy << 10;
            const int  srow = r * SP_;
            for (int cc = c; cc < Wt; cc += 32) {
                const int  gx = xmin + cc;
                const bool v  = vy && ((unsigned)gx < (unsigned)W_);
                const int  go = grow + gx;
                float v0 = 0.f, v1 = 0.f, v2 = 0.f;
                if (v) {
                    v0 = __ldg(x + go);
                    v1 = __ldg(x + HW_ + go);
                    v2 = __ldg(x + 2 * HW_ + go);
                }
                sm[srow + cc]            = v0;
                sm[SCH_ + srow + cc]     = v1;
                sm[2 * SCH_ + srow + cc] = v2;
            }
        }
    }
    __syncthreads();

    // ---- compute 32x32 tile ----
    const int tx = tid & 31;
    const int ty = tid >> 5;
    const float fw = (float)(w0 + tx) + 0.5f;
    const float px = fmaf(t00, fw, cx);
    const float py = fmaf(t10, fw, cy);

    float* xs0 = out + (size_t)n * 3 * HW_;
    float* xs1 = xs0 + HW_;
    float* xs2 = xs1 + HW_;
    float* oso = out + (size_t)NTR_ * 3 * HW_ + (size_t)n * HW_;

    #pragma unroll
    for (int k = 0; k < 4; ++k) {
        const int h = h0 + ty + (k << 3);
        const float fh = (float)h + 0.5f;
        const float ix = fmaf(t01, fh, px);
        const float iy = fmaf(t11, fh, py);

        const float x0f = floorf(ix);
        const float y0f = floorf(iy);
        const float wx1 = ix - x0f;
        const float wy1 = iy - y0f;
        const int x0 = (int)x0f;
        const int y0 = (int)y0f;

        const int soff = (y0 - ymin) * SP_ + (x0 - xmin);
        const float* s0 = sm + soff;

        // channel 0
        float a00 = s0[0], a10 = s0[1], a01 = s0[SP_], a11 = s0[SP_ + 1];
        float u0 = fmaf(wx1, a10 - a00, a00);
        float u1 = fmaf(wx1, a11 - a01, a01);
        float r0 = fmaf(wy1, u1 - u0, u0);
        // channel 1
        const float* s1 = s0 + SCH_;
        a00 = s1[0]; a10 = s1[1]; a01 = s1[SP_]; a11 = s1[SP_ + 1];
        u0 = fmaf(wx1, a10 - a00, a00);
        u1 = fmaf(wx1, a11 - a01, a01);
        float r1 = fmaf(wy1, u1 - u0, u0);
        // channel 2
        const float* s2 = s1 + SCH_;
        a00 = s2[0]; a10 = s2[1]; a01 = s2[SP_]; a11 = s2[SP_ + 1];
        u0 = fmaf(wx1, a10 - a00, a00);
        u1 = fmaf(wx1, a11 - a01, a01);
        float r2 = fmaf(wy1, u1 - u0, u0);

        // os = (wx0*vx0 + wx1*vx1) * (wy0*vy0 + wy1*vy1)
        const float ex0 = ((unsigned)x0       < (unsigned)W_) ? (1.0f - wx1) : 0.f;
        const float ex1 = ((unsigned)(x0 + 1) < (unsigned)W_) ? wx1 : 0.f;
        const float ey0 = ((unsigned)y0       < (unsigned)H_) ? (1.0f - wy1) : 0.f;
        const float ey1 = ((unsigned)(y0 + 1) < (unsigned)H_) ? wy1 : 0.f;
        const float ro = (ex0 + ex1) * (ey0 + ey1);

        const size_t o = ((size_t)h << 10) + (w0 + tx);
        xs0[o] = r0;
        xs1[o] = r1;
        xs2[o] = r2;
        oso[o] = ro;
    }
}

extern "C" void kernel_launch(void* const* d_in, const int* in_sizes, int n_in,
                              void* d_out, int out_size) {
    const float* x = (const float*)d_in[0];        // (1,3,1024,1024)
    const float* A = (const float*)d_in[1];        // (1,12,2,3)
    float* out = (float*)d_out;

    affine_params_kernel<<<1, 32>>>(A, out);
    dim3 grid(W_ / 32, H_ / 32, NTR_);
    sample_tile_kernel<<<grid, 256>>>(x, A, out);
}

// round 4
// speedup vs baseline: 1.7423x; 1.7423x over previous
#include <cuda_runtime.h>

#define HW_   1048576   // 1024*1024
#define W_    1024
#define H_    1024
#define NTR_  12

// Output float layout (out_size = 12*4*HW + 144):
//   xs   : [0, 12*3*HW)        (12,3,1024,1024)
//   os   : [12*3*HW, 12*4*HW)  (12,1,1024,1024)
//   z    : [12*4*HW, +72)   inv_z: [+72, +144)

// One block per (row h, transform n). 256 threads; each thread handles
// pixels w = p*256 + tid  -> lanes contiguous at every step.
// Warp-uniform interior fast path skips all clamp/validity work.
__global__ void __launch_bounds__(256)
sample_row_kernel(const float* __restrict__ x,
                  const float* __restrict__ A,
                  float* __restrict__ out) {
    const int n   = blockIdx.y;
    const int h   = blockIdx.x;
    const int tid = threadIdx.x;

    const float t00 = __ldg(A + n*6 + 0);
    const float t01 = __ldg(A + n*6 + 1);
    const float t02 = __ldg(A + n*6 + 2);
    const float t10 = __ldg(A + n*6 + 3);
    const float t11 = __ldg(A + n*6 + 4);
    const float t12 = __ldg(A + n*6 + 5);

    // Fold z / inv_z emission into this kernel (block h==0, one thread).
    if (h == 0 && tid == 0) {
        float* z  = out + (size_t)NTR_ * 4 * HW_ + n * 6;
        float* iz = z + NTR_ * 6;
        z[0] = t00; z[1] = t01; z[2] = t02;
        z[3] = t10; z[4] = t11; z[5] = t12;
        float inv = 1.0f / (t00 * t11 - t01 * t10);
        float ia =  t11 * inv, ib = -t01 * inv;
        float ic = -t10 * inv, id =  t00 * inv;
        iz[0] = ia; iz[1] = ib; iz[2] = -(ia * t02 + ib * t12);
        iz[3] = ic; iz[4] = id; iz[5] = -(ic * t02 + id * t12);
    }

    // ix = t00*(w+0.5) + t01*(h+0.5) + cx ; iy likewise
    const float cx = 512.0f * (t02 - t00 - t01 + 1.0f) - 0.5f;
    const float cy = 512.0f * (t12 - t10 - t11 + 1.0f) - 0.5f;
    const float fh = (float)h + 0.5f;
    const float hx = fmaf(t01, fh, cx);
    const float hy = fmaf(t11, fh, cy);

    const size_t row = (size_t)h * W_;
    float* xs0 = out + (size_t)n * 3 * HW_ + row;
    float* xs1 = xs0 + HW_;
    float* xs2 = xs1 + HW_;
    float* oso = out + (size_t)NTR_ * 3 * HW_ + (size_t)n * HW_ + row;

    const int lane_base = tid & ~31;   // warp's first tid (lane-uniform)

    #pragma unroll
    for (int p = 0; p < 4; ++p) {
        const int w = p * 256 + tid;
        const float fw = (float)w + 0.5f;
        const float ix = fmaf(t00, fw, hx);
        const float iy = fmaf(t10, fw, hy);

        const float x0f = floorf(ix);
        const float y0f = floorf(iy);
        const float wx1 = ix - x0f;
        const float wy1 = iy - y0f;
        const float wx0 = 1.0f - wx1;
        const float wy0 = 1.0f - wy1;
        const float w00 = wx0 * wy0;
        const float w10 = wx1 * wy0;
        const float w01 = wx0 * wy1;
        const float w11 = wx1 * wy1;

        const int x0 = (int)x0f, y0 = (int)y0f;

        // ---- warp-uniform interior test (lane-invariant operands) ----
        const float wbA = (float)(p * 256 + lane_base) + 0.5f;
        const float wbB = wbA + 31.0f;
        const float exA = fmaf(t00, wbA, hx), exB = fmaf(t00, wbB, hx);
        const float eyA = fmaf(t10, wbA, hy), eyB = fmaf(t10, wbB, hy);
        const float xlo = fminf(exA, exB), xhi = fmaxf(exA, exB);
        const float ylo = fminf(eyA, eyB), yhi = fmaxf(eyA, eyB);
        const bool interior = (xlo >= 1.0f) & (xhi <= 1021.0f) &
                              (ylo >= 1.0f) & (yhi <= 1021.0f);

        float r0, r1, r2, ro;
        if (interior) {
            const float* s = x + (y0 << 10) + x0;
            r0 = __ldg(s)             * w00 + __ldg(s + 1)             * w10
               + __ldg(s + W_)        * w01 + __ldg(s + W_ + 1)        * w11;
            r1 = __ldg(s + HW_)       * w00 + __ldg(s + HW_ + 1)       * w10
               + __ldg(s + HW_ + W_)  * w01 + __ldg(s + HW_ + W_ + 1)  * w11;
            r2 = __ldg(s + 2*HW_)     * w00 + __ldg(s + 2*HW_ + 1)     * w10
               + __ldg(s + 2*HW_ + W_)* w01 + __ldg(s + 2*HW_ + W_ + 1)* w11;
            ro = 1.0f;
        } else {
            const int x1 = x0 + 1, y1 = y0 + 1;
            const bool vx0 = ((unsigned)x0 < (unsigned)W_);
            const bool vx1 = ((unsigned)x1 < (unsigned)W_);
            const bool vy0 = ((unsigned)y0 < (unsigned)H_);
            const bool vy1 = ((unsigned)y1 < (unsigned)H_);

            const float m00 = w00 * (float)(vx0 && vy0);
            const float m10 = w10 * (float)(vx1 && vy0);
            const float m01 = w01 * (float)(vx0 && vy1);
            const float m11 = w11 * (float)(vx1 && vy1);

            const int xc0 = min(max(x0, 0), W_ - 1);
            const int xc1 = min(max(x1, 0), W_ - 1);
            const int yc0 = min(max(y0, 0), H_ - 1);
            const int yc1 = min(max(y1, 0), H_ - 1);

            const int o00 = (yc0 << 10) + xc0;
            const int o10 = (yc0 << 10) + xc1;
            const int o01 = (yc1 << 10) + xc0;
            const int o11 = (yc1 << 10) + xc1;

            r0 = __ldg(x + o00)         * m00 + __ldg(x + o10)         * m10
               + __ldg(x + o01)         * m01 + __ldg(x + o11)         * m11;
            r1 = __ldg(x + HW_ + o00)   * m00 + __ldg(x + HW_ + o10)   * m10
               + __ldg(x + HW_ + o01)   * m01 + __ldg(x + HW_ + o11)   * m11;
            r2 = __ldg(x + 2*HW_ + o00) * m00 + __ldg(x + 2*HW_ + o10) * m10
               + __ldg(x + 2*HW_ + o01) * m01 + __ldg(x + 2*HW_ + o11) * m11;
            ro = m00 + m10 + m01 + m11;
        }

        xs0[w] = r0;
        xs1[w] = r1;
        xs2[w] = r2;
        oso[w] = ro;
    }
}

extern "C" void kernel_launch(void* const* d_in, const int* in_sizes, int n_in,
                              void* d_out, int out_size) {
    const float* x = (const float*)d_in[0];        // (1,3,1024,1024)
    const float* A = (const float*)d_in[1];        // (1,12,2,3)
    float* out = (float*)d_out;

    dim3 grid(H_, NTR_);
    sample_row_kernel<<<grid, 256>>>(x, A, out);
}